// round 16
// baseline (speedup 1.0000x reference)
#include <cuda_runtime.h>
#include <cuda_bf16.h>
#include <mma.h>
#include <math.h>
#include <stdint.h>

using namespace nvcuda;

#define BQ   2
#define LQ   1024
#define DM   1024
#define DI   2048
#define DS   16
#define NROW (BQ*LQ)      // 2048
#define NC   16           // chunks
#define TCH  (LQ/NC)      // 64 steps per chunk
#define WXN  128          // padded N for the W_x gemm
#define KSPL 8            // split-K factor for xp gemm

// ---------------- scratch ----------------
__device__ __nv_bfloat16 g_xn[NROW*DM];
__device__ __nv_bfloat16 g_Win[DM*2*DI];
__device__ __nv_bfloat16 g_Wout[DI*DM];
__device__ __nv_bfloat16 g_Wx[DI*WXN];
__device__ float         g_xz[(size_t)NROW*2*DI];
__device__ __nv_bfloat16 g_xcb[(size_t)NROW*DI];
__device__ float         g_xpraw[(size_t)KSPL*NROW*WXN];
__device__ float         g_xpp[NROW*36];           // [0:16]=delta*B, [16:32]=C, [32]=delta, [33]=exp(-delta)
__device__ __nv_bfloat16 g_g[(size_t)NROW*DI];     // gated output (gemm2 A)
__device__ float         g_hfin[BQ*NC*DI*DS];
__device__ float         g_h0[BQ*NC*DI*DS];
__device__ float         g_S[BQ*NC];

// ---------------- fused weight converts ----------------
#define T1 (DM*2*DI)
#define T2 (DI*DM)
#define T3 (DI*WXN)
__global__ void cvt_all_k(const float* __restrict__ win,
                          const float* __restrict__ wout,
                          const float* __restrict__ wx) {
    int i = blockIdx.x*256 + threadIdx.x;
    if (i < T1) {
        g_Win[i] = __float2bfloat16(win[i]);
    } else if (i < T1+T2) {
        int j = i - T1;
        g_Wout[j] = __float2bfloat16(wout[j]);
    } else if (i < T1+T2+T3) {
        int j = i - T1 - T2;
        int k = j >> 7, n = j & (WXN-1);
        g_Wx[j] = __float2bfloat16(n < (2*DS+1) ? wx[k*(2*DS+1) + n] : 0.f);
    }
}

// ---------------- layernorm ----------------
__global__ void ln_k(const float* __restrict__ x, const float* __restrict__ w,
                     const float* __restrict__ b) {
    __shared__ float red[8];
    __shared__ float bcast;
    int r = blockIdx.x, tid = threadIdx.x;
    const float* xr = x + (size_t)r*DM;
    float v0 = xr[tid], v1 = xr[tid+256], v2 = xr[tid+512], v3 = xr[tid+768];
    float s = v0+v1+v2+v3;
    #pragma unroll
    for (int o=16;o;o>>=1) s += __shfl_xor_sync(0xffffffffu, s, o);
    if ((tid&31)==0) red[tid>>5] = s;
    __syncthreads();
    if (tid==0) {
        float t = red[0]+red[1]+red[2]+red[3]+red[4]+red[5]+red[6]+red[7];
        bcast = t*(1.f/DM);
    }
    __syncthreads();
    float mu = bcast;
    float d0=v0-mu, d1=v1-mu, d2=v2-mu, d3=v3-mu;
    float q = d0*d0+d1*d1+d2*d2+d3*d3;
    __syncthreads();
    #pragma unroll
    for (int o=16;o;o>>=1) q += __shfl_xor_sync(0xffffffffu, q, o);
    if ((tid&31)==0) red[tid>>5] = q;
    __syncthreads();
    if (tid==0) {
        float t = red[0]+red[1]+red[2]+red[3]+red[4]+red[5]+red[6]+red[7];
        bcast = rsqrtf(t*(1.f/DM) + 1e-5f);
    }
    __syncthreads();
    float inv = bcast;
    __nv_bfloat16* o = g_xn + (size_t)r*DM;
    o[tid    ] = __float2bfloat16(d0*inv*w[tid    ] + b[tid    ]);
    o[tid+256] = __float2bfloat16(d1*inv*w[tid+256] + b[tid+256]);
    o[tid+512] = __float2bfloat16(d2*inv*w[tid+512] + b[tid+512]);
    o[tid+768] = __float2bfloat16(d3*inv*w[tid+768] + b[tid+768]);
}

// ---------------- pipelined bf16 wmma GEMM, BK=64, dynamic smem ----------------
#define BM 128
#define BN 128
#define BK 64
#define AP 8
#define BP 16
#define ASTR (BK+AP)
#define BSTR (BN+BP)
#define AST  (BM*ASTR)
#define BST  (BK*BSTR)
#define GSMEM ((2*AST + 2*BST) * 2)

__device__ __forceinline__ void cpa16(void* dst_smem, const void* src_gmem) {
    unsigned d = (unsigned)__cvta_generic_to_shared(dst_smem);
    asm volatile("cp.async.cg.shared.global [%0], [%1], 16;" :: "r"(d), "l"(src_gmem));
}

__global__ void __launch_bounds__(128) gemm_k(const __nv_bfloat16* __restrict__ A,
                                              const __nv_bfloat16* __restrict__ B,
                                              float* __restrict__ C,
                                              const float* __restrict__ Cinit,
                                              int N, int K, int kchunk, size_t cstride) {
    extern __shared__ __nv_bfloat16 sm[];
    __nv_bfloat16* Asm = sm;
    __nv_bfloat16* Bsm = sm + 2*AST;
    int bx = blockIdx.x, by = blockIdx.y, bz = blockIdx.z;
    int tid = threadIdx.x;
    int warp = tid >> 5;
    int wm = warp & 1;
    int wn = warp >> 1;
    int kbeg = bz * kchunk;
    C += (size_t)bz * cstride;

    wmma::fragment<wmma::accumulator,16,16,16,float> acc[4][4];
    if (Cinit) {
        #pragma unroll
        for (int i=0;i<4;i++)
            #pragma unroll
            for (int j=0;j<4;j++)
                wmma::load_matrix_sync(acc[i][j],
                    &Cinit[(size_t)(by*BM+wm*64+i*16)*N + bx*BN+wn*64+j*16],
                    N, wmma::mem_row_major);
    } else {
        #pragma unroll
        for (int i=0;i<4;i++)
            #pragma unroll
            for (int j=0;j<4;j++) wmma::fill_fragment(acc[i][j], 0.f);
    }

    const __nv_bfloat16* Abase = A + (size_t)(by*BM)*K + kbeg;
    const __nv_bfloat16* Bbase = B + (size_t)kbeg*N + bx*BN;

    auto load_tile = [&](int s, int koff) {
        #pragma unroll
        for (int u=0; u<8; u++) {
            int idx = tid + u*128;
            int ar = idx >> 3, ac = idx & 7;
            cpa16(&Asm[s*AST + ar*ASTR + ac*8], Abase + (size_t)ar*K + koff + ac*8);
        }
        #pragma unroll
        for (int u=0; u<8; u++) {
            int idx = tid + u*128;
            int br = idx >> 4, bc = idx & 15;
            cpa16(&Bsm[s*BST + br*BSTR + bc*8], Bbase + (size_t)(koff+br)*N + bc*8);
        }
        asm volatile("cp.async.commit_group;");
    };

    int ntiles = kchunk / BK;
    load_tile(0, 0);

    for (int it = 0; it < ntiles; it++) {
        if (it + 1 < ntiles) {
            load_tile((it+1)&1, (it+1)*BK);
            asm volatile("cp.async.wait_group 1;");
        } else {
            asm volatile("cp.async.wait_group 0;");
        }
        __syncthreads();
        int s = it & 1;
        const __nv_bfloat16* Ap = &Asm[s*AST + wm*64*ASTR];
        const __nv_bfloat16* Bp = &Bsm[s*BST + wn*64];
        #pragma unroll
        for (int kk=0; kk<BK; kk+=16) {
            wmma::fragment<wmma::matrix_a,16,16,16,__nv_bfloat16,wmma::row_major> af[4];
            wmma::fragment<wmma::matrix_b,16,16,16,__nv_bfloat16,wmma::row_major> bf[4];
            #pragma unroll
            for (int i=0;i<4;i++) wmma::load_matrix_sync(af[i], Ap + i*16*ASTR + kk, ASTR);
            #pragma unroll
            for (int j=0;j<4;j++) wmma::load_matrix_sync(bf[j], Bp + kk*BSTR + j*16, BSTR);
            #pragma unroll
            for (int i=0;i<4;i++)
                #pragma unroll
                for (int j=0;j<4;j++) wmma::mma_sync(acc[i][j], af[i], bf[j], acc[i][j]);
        }
        __syncthreads();
    }

    #pragma unroll
    for (int i=0;i<4;i++)
        #pragma unroll
        for (int j=0;j<4;j++)
            wmma::store_matrix_sync(&C[(size_t)(by*BM+wm*64+i*16)*N + bx*BN+wn*64+j*16],
                                    acc[i][j], N, wmma::mem_row_major);
}

// ---------------- depthwise causal conv (k=4) + silu, bf16 out only ----------------
#define CL 8
__global__ void conv_k(const float* __restrict__ cw, const float* __restrict__ cb) {
    int d  = blockIdx.x*256 + threadIdx.x;
    int r0 = blockIdx.y * CL;
    int l0 = r0 & (LQ-1);
    float w0 = cw[d*4+0], w1 = cw[d*4+1], w2 = cw[d*4+2], w3 = cw[d*4+3];
    float bb = cb[d];
    float v[CL+3];
    #pragma unroll
    for (int i=0; i<CL+3; i++) {
        int l = l0 + i - 3;
        v[i] = (l >= 0) ? g_xz[(size_t)(r0 + i - 3)*(2*DI) + d] : 0.f;
    }
    #pragma unroll
    for (int j=0; j<CL; j++) {
        float acc = bb;
        acc = fmaf(v[j  ], w0, acc);
        acc = fmaf(v[j+1], w1, acc);
        acc = fmaf(v[j+2], w2, acc);
        acc = fmaf(v[j+3], w3, acc);
        float sv = acc / (1.f + __expf(-acc));
        g_xcb[(size_t)(r0+j)*DI + d] = __float2bfloat16(sv);
    }
}

// ---------------- xp postprocess ----------------
__global__ void xpost_k() {
    __shared__ float sd;
    int r = blockIdx.x, tid = threadIdx.x;
    float v = 0.f;
    if (tid < 33) {
        #pragma unroll
        for (int s=0; s<KSPL; s++)
            v += g_xpraw[(size_t)s*NROW*WXN + r*WXN + tid];
    }
    if (tid == 32) {
        float dl = (v > 20.f) ? v : log1pf(__expf(v));
        sd = dl;
        g_xpp[r*36 + 32] = dl;
        g_xpp[r*36 + 33] = __expf(-dl);
    }
    __syncthreads();
    if (tid < 16)       g_xpp[r*36 + tid] = v * sd;
    else if (tid < 32)  g_xpp[r*36 + tid] = v;
}

// ---------------- per-chunk delta sums (TCH=64 -> 2 warps) ----------------
__global__ void sums_k() {
    __shared__ float red[2];
    int bc = blockIdx.x, t = threadIdx.x;
    int b = bc / NC, c = bc % NC;
    float v = g_xpp[(size_t)((b*LQ + c*TCH + t))*36 + 32];
    #pragma unroll
    for (int o=16;o;o>>=1) v += __shfl_xor_sync(0xffffffffu, v, o);
    if ((t&31)==0) red[t>>5] = v;
    __syncthreads();
    if (t==0) g_S[bc] = red[0]+red[1];
}

__device__ __forceinline__ bool an_is_seq(const float* An) {
    bool ok = true;
    #pragma unroll
    for (int n=0;n<DS;n++) ok &= (fabsf(An[n] + (float)(n+1)) < 1e-3f*(n+1));
    return ok;
}

// ---------------- scan pass A: smem-staged xpp (float2 reads), fused gate ----------------
__global__ void __launch_bounds__(256) scanA_k(const float* __restrict__ logA,
                                               const float* __restrict__ Dp) {
    __shared__ __align__(8) float sxpp[TCH*36];    // whole chunk's xpp block (9KB)
    int d = blockIdx.x*256 + threadIdx.x;
    int b = blockIdx.y, c = blockIdx.z;
    int tid = threadIdx.x;
    int rbase = b*LQ + c*TCH;

    {
        const float4* src = (const float4*)(g_xpp + (size_t)rbase*36);
        float4* dst = (float4*)sxpp;
        for (int i = tid; i < TCH*9; i += 256) dst[i] = src[i];
    }

    float An[DS], h[DS];
    #pragma unroll
    for (int n=0;n<DS;n++) { An[n] = -__expf(logA[d*DS+n]); h[n] = 0.f; }
    bool fast = an_is_seq(An);
    float Dd = Dp[d];
    __syncthreads();

    float xv_c = __bfloat162float(g_xcb[(size_t)rbase*DI + d]);
    float zv_c = g_xz[(size_t)rbase*(2*DI) + DI + d];

    for (int t=0; t<TCH; t++) {
        int r = rbase + t;
        float xv = xv_c, zv = zv_c;
        if (t+1 < TCH) {                           // prefetch next xv/zv
            xv_c = __bfloat162float(g_xcb[(size_t)(r+1)*DI + d]);
            zv_c = g_xz[(size_t)(r+1)*(2*DI) + DI + d];
        }
        const float* p = &sxpp[t*36];
        float2 dp = *(const float2*)&p[32];        // x=delta, y=pw
        float delta = dp.x, pw = dp.y;
        float y = Dd * xv;
        if (fast) {
            float pk = pw;
            #pragma unroll
            for (int n=0;n<DS;n+=2) {              // float2 reads, consumed immediately
                float2 dBp = *(const float2*)&p[n];
                float2 Ccp = *(const float2*)&p[16+n];
                h[n]   = fmaf(pk, h[n],   dBp.x*xv);
                y      = fmaf(h[n],   Ccp.x, y);
                pk    *= pw;
                h[n+1] = fmaf(pk, h[n+1], dBp.y*xv);
                y      = fmaf(h[n+1], Ccp.y, y);
                pk    *= pw;
            }
        } else {
            #pragma unroll
            for (int n=0;n<DS;n++) {
                float dA = __expf(delta * An[n]);
                h[n] = fmaf(dA, h[n], p[n]*xv);
                y    = fmaf(h[n], p[16+n], y);
            }
        }
        float sz = zv / (1.f + __expf(-zv));
        g_g[(size_t)r*DI + d] = __float2bfloat16(y * sz);
    }
    float* hf = g_hfin + ((size_t)(b*NC+c)*DI + d)*DS;
    #pragma unroll
    for (int n=0;n<DS;n++) hf[n] = h[n];
}

// ---------------- scan pass B: propagate chunk-entry states ----------------
__global__ void scanB_k(const float* __restrict__ logA, const float* __restrict__ init_state) {
    int idx = blockIdx.x*256 + threadIdx.x;
    int n = idx & 15;
    int d = (idx >> 4) & (DI-1);
    int b = idx >> 15;
    float An = -__expf(logA[d*DS+n]);
    float h0 = init_state[idx];
    #pragma unroll
    for (int c=0;c<NC;c++) {
        g_h0[((size_t)(b*NC+c)*DI + d)*DS + n] = h0;
        float P = __expf(An * g_S[b*NC+c]);
        h0 = fmaf(P, h0, g_hfin[((size_t)(b*NC+c)*DI + d)*DS + n]);
    }
}

// ---------------- scan pass C: smem-staged xpp (float2 reads), RMW gate ----------------
__global__ void __launch_bounds__(256) scanC_k(const float* __restrict__ logA) {
    __shared__ __align__(8) float sxpp[TCH*36];
    int d = blockIdx.x*256 + threadIdx.x;
    int b = blockIdx.y, c = blockIdx.z;
    int tid = threadIdx.x;
    int rbase = b*LQ + c*TCH;

    {
        const float4* src = (const float4*)(g_xpp + (size_t)rbase*36);
        float4* dst = (float4*)sxpp;
        for (int i = tid; i < TCH*9; i += 256) dst[i] = src[i];
    }

    float An[DS], hc[DS];
    const float* h0p = g_h0 + ((size_t)(b*NC+c)*DI + d)*DS;
    float ss = 0.f;
    #pragma unroll
    for (int n=0;n<DS;n++) {
        An[n] = -__expf(logA[d*DS+n]);
        hc[n] = h0p[n];
        ss += fabsf(hc[n]);
    }
    bool fast = an_is_seq(An);
    __syncthreads();
    if (__all_sync(0xffffffffu, ss < 1e-30f)) return;

    for (int t=0; t<TCH; t++) {
        int r = rbase + t;
        const float* p = &sxpp[t*36];
        float2 dp = *(const float2*)&p[32];
        float delta = dp.x, pw = dp.y;
        float y = 0.f; ss = 0.f;
        if (fast) {
            float pk = pw;
            #pragma unroll
            for (int n=0;n<DS;n+=2) {
                float2 Ccp = *(const float2*)&p[16+n];
                hc[n]   *= pk;
                y        = fmaf(hc[n],   Ccp.x, y);
                ss      += fabsf(hc[n]);
                pk      *= pw;
                hc[n+1] *= pk;
                y        = fmaf(hc[n+1], Ccp.y, y);
                ss      += fabsf(hc[n+1]);
                pk      *= pw;
            }
        } else {
            #pragma unroll
            for (int n=0;n<DS;n++) {
                hc[n] *= __expf(delta * An[n]);
                y  = fmaf(hc[n], p[16+n], y);
                ss += fabsf(hc[n]);
            }
        }
        float zv = g_xz[(size_t)r*(2*DI) + DI + d];
        float sz = zv / (1.f + __expf(-zv));
        size_t gi = (size_t)r*DI + d;
        g_g[gi] = __float2bfloat16(__bfloat162float(g_g[gi]) + y * sz);
        if (__all_sync(0xffffffffu, ss < 1e-28f)) break;
    }
}

// ---------------- launch ----------------
extern "C" void kernel_launch(void* const* d_in, const int* in_sizes, int n_in,
                              void* d_out, int out_size) {
    const float* x          = (const float*)d_in[0];
    const float* init_state = (const float*)d_in[1];
    const float* ln_w       = (const float*)d_in[2];
    const float* ln_b       = (const float*)d_in[3];
    const float* W_in       = (const float*)d_in[4];
    const float* conv_w     = (const float*)d_in[5];
    const float* conv_b     = (const float*)d_in[6];
    const float* W_x        = (const float*)d_in[7];
    const float* log_A      = (const float*)d_in[8];
    const float* D_param    = (const float*)d_in[9];
    const float* W_out      = (const float*)d_in[10];
    float* out = (float*)d_out;

    void *p_xn, *p_Win, *p_Wout, *p_Wx, *p_xz, *p_xcb, *p_xpraw, *p_g;
    cudaGetSymbolAddress(&p_xn,    g_xn);
    cudaGetSymbolAddress(&p_Win,   g_Win);
    cudaGetSymbolAddress(&p_Wout,  g_Wout);
    cudaGetSymbolAddress(&p_Wx,    g_Wx);
    cudaGetSymbolAddress(&p_xz,    g_xz);
    cudaGetSymbolAddress(&p_xcb,   g_xcb);
    cudaGetSymbolAddress(&p_xpraw, g_xpraw);
    cudaGetSymbolAddress(&p_g,     g_g);

    static int smem_set = 0;
    if (!smem_set) {
        cudaFuncSetAttribute(gemm_k, cudaFuncAttributeMaxDynamicSharedMemorySize, GSMEM);
        smem_set = 1;
    }

    cvt_all_k<<<(T1+T2+T3+255)/256, 256>>>(W_in, W_out, W_x);

    ln_k<<<NROW, 256>>>(x, ln_w, ln_b);

    // GEMM1: xz[2048,4096] = xn[2048,1024] @ W_in[1024,4096]
    gemm_k<<<dim3(2*DI/BN, NROW/BM, 1), 128, GSMEM>>>((const __nv_bfloat16*)p_xn,
                                                      (const __nv_bfloat16*)p_Win,
                                                      (float*)p_xz, nullptr, 2*DI, DM, DM, 0);

    conv_k<<<dim3(DI/256, NROW/CL), 256>>>(conv_w, conv_b);

    // xp GEMM (split-K=8)
    gemm_k<<<dim3(WXN/BN, NROW/BM, KSPL), 128, GSMEM>>>((const __nv_bfloat16*)p_xcb,
                                                        (const __nv_bfloat16*)p_Wx,
                                                        (float*)p_xpraw, nullptr, WXN, DI, DI/KSPL,
                                                        (size_t)NROW*WXN);

    xpost_k<<<NROW, 64>>>();
    sums_k<<<BQ*NC, TCH>>>();

    scanA_k<<<dim3(DI/256, BQ, NC), 256>>>(log_A, D_param);
    scanB_k<<<(BQ*DI*DS)/256, 256>>>(log_A, init_state);
    scanC_k<<<dim3(DI/256, BQ, NC), 256>>>(log_A);

    // GEMM2 (+fused residual): out = x + g[2048,2048] @ W_out[2048,1024]
    gemm_k<<<dim3(DM/BN, NROW/BM, 1), 128, GSMEM>>>((const __nv_bfloat16*)p_g,
                                                    (const __nv_bfloat16*)p_Wout,
                                                    out, x, DM, DI, DI, 0);
}

// round 17
// speedup vs baseline: 1.0173x; 1.0173x over previous
#include <cuda_runtime.h>
#include <cuda_bf16.h>
#include <mma.h>
#include <math.h>
#include <stdint.h>

using namespace nvcuda;

#define BQ   2
#define LQ   1024
#define DM   1024
#define DI   2048
#define DS   16
#define NROW (BQ*LQ)      // 2048
#define NC   16           // chunks
#define TCH  (LQ/NC)      // 64 steps per chunk
#define WXN  128          // padded N for the W_x gemm
#define KSPL 8            // split-K factor for xp gemm

// ---------------- scratch ----------------
__device__ __nv_bfloat16 g_xn[NROW*DM];
__device__ __nv_bfloat16 g_Win[DM*2*DI];
__device__ __nv_bfloat16 g_Wout[DI*DM];
__device__ __nv_bfloat16 g_Wx[DI*WXN];
__device__ float         g_xz[(size_t)NROW*2*DI];
__device__ float         g_xc[(size_t)NROW*DI];
__device__ __nv_bfloat16 g_xcb[(size_t)NROW*DI];
__device__ float         g_xpraw[(size_t)KSPL*NROW*WXN];
__device__ float         g_xpp[NROW*36];           // [0:16]=delta*B, [16:32]=C, [32]=delta, [33]=exp(-delta)
__device__ __nv_bfloat16 g_g[(size_t)NROW*DI];     // gated output (gemm2 A)
__device__ float         g_hfin[BQ*NC*DI*DS];
__device__ float         g_h0[BQ*NC*DI*DS];
__device__ float         g_S[BQ*NC];

// ---------------- fused weight converts ----------------
#define T1 (DM*2*DI)
#define T2 (DI*DM)
#define T3 (DI*WXN)
__global__ void cvt_all_k(const float* __restrict__ win,
                          const float* __restrict__ wout,
                          const float* __restrict__ wx) {
    int i = blockIdx.x*256 + threadIdx.x;
    if (i < T1) {
        g_Win[i] = __float2bfloat16(win[i]);
    } else if (i < T1+T2) {
        int j = i - T1;
        g_Wout[j] = __float2bfloat16(wout[j]);
    } else if (i < T1+T2+T3) {
        int j = i - T1 - T2;
        int k = j >> 7, n = j & (WXN-1);
        g_Wx[j] = __float2bfloat16(n < (2*DS+1) ? wx[k*(2*DS+1) + n] : 0.f);
    }
}

// ---------------- layernorm ----------------
__global__ void ln_k(const float* __restrict__ x, const float* __restrict__ w,
                     const float* __restrict__ b) {
    __shared__ float red[8];
    __shared__ float bcast;
    int r = blockIdx.x, tid = threadIdx.x;
    const float* xr = x + (size_t)r*DM;
    float v0 = xr[tid], v1 = xr[tid+256], v2 = xr[tid+512], v3 = xr[tid+768];
    float s = v0+v1+v2+v3;
    #pragma unroll
    for (int o=16;o;o>>=1) s += __shfl_xor_sync(0xffffffffu, s, o);
    if ((tid&31)==0) red[tid>>5] = s;
    __syncthreads();
    if (tid==0) {
        float t = red[0]+red[1]+red[2]+red[3]+red[4]+red[5]+red[6]+red[7];
        bcast = t*(1.f/DM);
    }
    __syncthreads();
    float mu = bcast;
    float d0=v0-mu, d1=v1-mu, d2=v2-mu, d3=v3-mu;
    float q = d0*d0+d1*d1+d2*d2+d3*d3;
    __syncthreads();
    #pragma unroll
    for (int o=16;o;o>>=1) q += __shfl_xor_sync(0xffffffffu, q, o);
    if ((tid&31)==0) red[tid>>5] = q;
    __syncthreads();
    if (tid==0) {
        float t = red[0]+red[1]+red[2]+red[3]+red[4]+red[5]+red[6]+red[7];
        bcast = rsqrtf(t*(1.f/DM) + 1e-5f);
    }
    __syncthreads();
    float inv = bcast;
    __nv_bfloat16* o = g_xn + (size_t)r*DM;
    o[tid    ] = __float2bfloat16(d0*inv*w[tid    ] + b[tid    ]);
    o[tid+256] = __float2bfloat16(d1*inv*w[tid+256] + b[tid+256]);
    o[tid+512] = __float2bfloat16(d2*inv*w[tid+512] + b[tid+512]);
    o[tid+768] = __float2bfloat16(d3*inv*w[tid+768] + b[tid+768]);
}

// ---------------- pipelined bf16 wmma GEMM, BK=64, dynamic smem ----------------
#define BM 128
#define BN 128
#define BK 64
#define AP 8
#define BP 16
#define ASTR (BK+AP)
#define BSTR (BN+BP)
#define AST  (BM*ASTR)
#define BST  (BK*BSTR)
#define GSMEM ((2*AST + 2*BST) * 2)

__device__ __forceinline__ void cpa16(void* dst_smem, const void* src_gmem) {
    unsigned d = (unsigned)__cvta_generic_to_shared(dst_smem);
    asm volatile("cp.async.cg.shared.global [%0], [%1], 16;" :: "r"(d), "l"(src_gmem));
}

__global__ void __launch_bounds__(128) gemm_k(const __nv_bfloat16* __restrict__ A,
                                              const __nv_bfloat16* __restrict__ B,
                                              float* __restrict__ C,
                                              const float* __restrict__ Cinit,
                                              int N, int K, int kchunk, size_t cstride) {
    extern __shared__ __nv_bfloat16 sm[];
    __nv_bfloat16* Asm = sm;
    __nv_bfloat16* Bsm = sm + 2*AST;
    int bx = blockIdx.x, by = blockIdx.y, bz = blockIdx.z;
    int tid = threadIdx.x;
    int warp = tid >> 5;
    int wm = warp & 1;
    int wn = warp >> 1;
    int kbeg = bz * kchunk;
    C += (size_t)bz * cstride;

    wmma::fragment<wmma::accumulator,16,16,16,float> acc[4][4];
    if (Cinit) {
        #pragma unroll
        for (int i=0;i<4;i++)
            #pragma unroll
            for (int j=0;j<4;j++)
                wmma::load_matrix_sync(acc[i][j],
                    &Cinit[(size_t)(by*BM+wm*64+i*16)*N + bx*BN+wn*64+j*16],
                    N, wmma::mem_row_major);
    } else {
        #pragma unroll
        for (int i=0;i<4;i++)
            #pragma unroll
            for (int j=0;j<4;j++) wmma::fill_fragment(acc[i][j], 0.f);
    }

    const __nv_bfloat16* Abase = A + (size_t)(by*BM)*K + kbeg;
    const __nv_bfloat16* Bbase = B + (size_t)kbeg*N + bx*BN;

    auto load_tile = [&](int s, int koff) {
        #pragma unroll
        for (int u=0; u<8; u++) {
            int idx = tid + u*128;
            int ar = idx >> 3, ac = idx & 7;
            cpa16(&Asm[s*AST + ar*ASTR + ac*8], Abase + (size_t)ar*K + koff + ac*8);
        }
        #pragma unroll
        for (int u=0; u<8; u++) {
            int idx = tid + u*128;
            int br = idx >> 4, bc = idx & 15;
            cpa16(&Bsm[s*BST + br*BSTR + bc*8], Bbase + (size_t)(koff+br)*N + bc*8);
        }
        asm volatile("cp.async.commit_group;");
    };

    int ntiles = kchunk / BK;
    load_tile(0, 0);

    for (int it = 0; it < ntiles; it++) {
        if (it + 1 < ntiles) {
            load_tile((it+1)&1, (it+1)*BK);
            asm volatile("cp.async.wait_group 1;");
        } else {
            asm volatile("cp.async.wait_group 0;");
        }
        __syncthreads();
        int s = it & 1;
        const __nv_bfloat16* Ap = &Asm[s*AST + wm*64*ASTR];
        const __nv_bfloat16* Bp = &Bsm[s*BST + wn*64];
        #pragma unroll
        for (int kk=0; kk<BK; kk+=16) {
            wmma::fragment<wmma::matrix_a,16,16,16,__nv_bfloat16,wmma::row_major> af[4];
            wmma::fragment<wmma::matrix_b,16,16,16,__nv_bfloat16,wmma::row_major> bf[4];
            #pragma unroll
            for (int i=0;i<4;i++) wmma::load_matrix_sync(af[i], Ap + i*16*ASTR + kk, ASTR);
            #pragma unroll
            for (int j=0;j<4;j++) wmma::load_matrix_sync(bf[j], Bp + kk*BSTR + j*16, BSTR);
            #pragma unroll
            for (int i=0;i<4;i++)
                #pragma unroll
                for (int j=0;j<4;j++) wmma::mma_sync(acc[i][j], af[i], bf[j], acc[i][j]);
        }
        __syncthreads();
    }

    #pragma unroll
    for (int i=0;i<4;i++)
        #pragma unroll
        for (int j=0;j<4;j++)
            wmma::store_matrix_sync(&C[(size_t)(by*BM+wm*64+i*16)*N + bx*BN+wn*64+j*16],
                                    acc[i][j], N, wmma::mem_row_major);
}

// ---------------- depthwise causal conv (k=4) + silu, 16 outputs/thread ----------------
#define CL 16
__global__ void conv_k(const float* __restrict__ cw, const float* __restrict__ cb) {
    int d  = blockIdx.x*256 + threadIdx.x;
    int r0 = blockIdx.y * CL;
    int l0 = r0 & (LQ-1);
    float w0 = cw[d*4+0], w1 = cw[d*4+1], w2 = cw[d*4+2], w3 = cw[d*4+3];
    float bb = cb[d];
    float v[CL+3];
    #pragma unroll
    for (int i=0; i<CL+3; i++) {
        int l = l0 + i - 3;
        v[i] = (l >= 0) ? g_xz[(size_t)(r0 + i - 3)*(2*DI) + d] : 0.f;
    }
    #pragma unroll
    for (int j=0; j<CL; j++) {
        float acc = bb;
        acc = fmaf(v[j  ], w0, acc);
        acc = fmaf(v[j+1], w1, acc);
        acc = fmaf(v[j+2], w2, acc);
        acc = fmaf(v[j+3], w3, acc);
        float sv = acc / (1.f + __expf(-acc));
        g_xc[(size_t)(r0+j)*DI + d]  = sv;
        g_xcb[(size_t)(r0+j)*DI + d] = __float2bfloat16(sv);
    }
}

// ---------------- xp postprocess ----------------
__global__ void xpost_k() {
    __shared__ float sd;
    int r = blockIdx.x, tid = threadIdx.x;
    float v = 0.f;
    if (tid < 33) {
        #pragma unroll
        for (int s=0; s<KSPL; s++)
            v += g_xpraw[(size_t)s*NROW*WXN + r*WXN + tid];
    }
    if (tid == 32) {
        float dl = (v > 20.f) ? v : log1pf(__expf(v));
        sd = dl;
        g_xpp[r*36 + 32] = dl;
        g_xpp[r*36 + 33] = __expf(-dl);
    }
    __syncthreads();
    if (tid < 16)       g_xpp[r*36 + tid] = v * sd;
    else if (tid < 32)  g_xpp[r*36 + tid] = v;
}

// ---------------- per-chunk delta sums (TCH=64 -> 2 warps) ----------------
__global__ void sums_k() {
    __shared__ float red[2];
    int bc = blockIdx.x, t = threadIdx.x;
    int b = bc / NC, c = bc % NC;
    float v = g_xpp[(size_t)((b*LQ + c*TCH + t))*36 + 32];
    #pragma unroll
    for (int o=16;o;o>>=1) v += __shfl_xor_sync(0xffffffffu, v, o);
    if ((t&31)==0) red[t>>5] = v;
    __syncthreads();
    if (t==0) g_S[bc] = red[0]+red[1];
}

__device__ __forceinline__ bool an_is_seq(const float* An) {
    bool ok = true;
    #pragma unroll
    for (int n=0;n<DS;n++) ok &= (fabsf(An[n] + (float)(n+1)) < 1e-3f*(n+1));
    return ok;
}

// ---------------- scan pass A: smem-staged xpp, fused gate ----------------
__global__ void __launch_bounds__(256) scanA_k(const float* __restrict__ logA,
                                               const float* __restrict__ Dp) {
    __shared__ float sxpp[TCH*36];                 // whole chunk's xpp block (9KB)
    int d = blockIdx.x*256 + threadIdx.x;
    int b = blockIdx.y, c = blockIdx.z;
    int tid = threadIdx.x;
    int rbase = b*LQ + c*TCH;

    // cooperative stage: contiguous [rbase*36, rbase*36 + TCH*36)
    {
        const float4* src = (const float4*)(g_xpp + (size_t)rbase*36);
        float4* dst = (float4*)sxpp;
        for (int i = tid; i < TCH*9; i += 256) dst[i] = src[i];
    }

    float An[DS], h[DS];
    #pragma unroll
    for (int n=0;n<DS;n++) { An[n] = -__expf(logA[d*DS+n]); h[n] = 0.f; }
    bool fast = an_is_seq(An);
    float Dd = Dp[d];
    __syncthreads();

    float xv_c = g_xc[(size_t)rbase*DI + d];
    float zv_c = g_xz[(size_t)rbase*(2*DI) + DI + d];

    for (int t=0; t<TCH; t++) {
        int r = rbase + t;
        float xv = xv_c, zv = zv_c;
        if (t+1 < TCH) {                           // prefetch next xv/zv
            xv_c = g_xc[(size_t)(r+1)*DI + d];
            zv_c = g_xz[(size_t)(r+1)*(2*DI) + DI + d];
        }
        const float* p = &sxpp[t*36];
        float delta = p[32], pw = p[33];
        float y = Dd * xv;
        if (fast) {
            float pk = pw;
            #pragma unroll
            for (int n=0;n<DS;n++) {
                h[n] = fmaf(pk, h[n], p[n]*xv);
                y    = fmaf(h[n], p[16+n], y);
                pk  *= pw;
            }
        } else {
            #pragma unroll
            for (int n=0;n<DS;n++) {
                float dA = __expf(delta * An[n]);
                h[n] = fmaf(dA, h[n], p[n]*xv);
                y    = fmaf(h[n], p[16+n], y);
            }
        }
        float sz = zv / (1.f + __expf(-zv));
        g_g[(size_t)r*DI + d] = __float2bfloat16(y * sz);
    }
    float* hf = g_hfin + ((size_t)(b*NC+c)*DI + d)*DS;
    #pragma unroll
    for (int n=0;n<DS;n++) hf[n] = h[n];
}

// ---------------- scan pass B: propagate chunk-entry states ----------------
__global__ void scanB_k(const float* __restrict__ logA, const float* __restrict__ init_state) {
    int idx = blockIdx.x*256 + threadIdx.x;
    int n = idx & 15;
    int d = (idx >> 4) & (DI-1);
    int b = idx >> 15;
    float An = -__expf(logA[d*DS+n]);
    float h0 = init_state[idx];
    #pragma unroll
    for (int c=0;c<NC;c++) {
        g_h0[((size_t)(b*NC+c)*DI + d)*DS + n] = h0;
        float P = __expf(An * g_S[b*NC+c]);
        h0 = fmaf(P, h0, g_hfin[((size_t)(b*NC+c)*DI + d)*DS + n]);
    }
}

// ---------------- scan pass C: smem-staged xpp, decay correction, RMW gate ----------------
__global__ void __launch_bounds__(256) scanC_k(const float* __restrict__ logA) {
    __shared__ float sxpp[TCH*36];
    int d = blockIdx.x*256 + threadIdx.x;
    int b = blockIdx.y, c = blockIdx.z;
    int tid = threadIdx.x;
    int rbase = b*LQ + c*TCH;

    {
        const float4* src = (const float4*)(g_xpp + (size_t)rbase*36);
        float4* dst = (float4*)sxpp;
        for (int i = tid; i < TCH*9; i += 256) dst[i] = src[i];
    }

    float An[DS], hc[DS];
    const float* h0p = g_h0 + ((size_t)(b*NC+c)*DI + d)*DS;
    float ss = 0.f;
    #pragma unroll
    for (int n=0;n<DS;n++) {
        An[n] = -__expf(logA[d*DS+n]);
        hc[n] = h0p[n];
        ss += fabsf(hc[n]);
    }
    bool fast = an_is_seq(An);
    __syncthreads();
    if (__all_sync(0xffffffffu, ss < 1e-30f)) return;

    for (int t=0; t<TCH; t++) {
        int r = rbase + t;
        const float* p = &sxpp[t*36];
        float delta = p[32], pw = p[33];
        float y = 0.f; ss = 0.f;
        if (fast) {
            float pk = pw;
            #pragma unroll
            for (int n=0;n<DS;n++) {
                hc[n] *= pk;
                y  = fmaf(hc[n], p[16+n], y);
                ss += fabsf(hc[n]);
                pk *= pw;
            }
        } else {
            #pragma unroll
            for (int n=0;n<DS;n++) {
                hc[n] *= __expf(delta * An[n]);
                y  = fmaf(hc[n], p[16+n], y);
                ss += fabsf(hc[n]);
            }
        }
        float zv = g_xz[(size_t)r*(2*DI) + DI + d];
        float sz = zv / (1.f + __expf(-zv));
        size_t gi = (size_t)r*DI + d;
        g_g[gi] = __float2bfloat16(__bfloat162float(g_g[gi]) + y * sz);
        if (__all_sync(0xffffffffu, ss < 1e-28f)) break;
    }
}

// ---------------- launch ----------------
extern "C" void kernel_launch(void* const* d_in, const int* in_sizes, int n_in,
                              void* d_out, int out_size) {
    const float* x          = (const float*)d_in[0];
    const float* init_state = (const float*)d_in[1];
    const float* ln_w       = (const float*)d_in[2];
    const float* ln_b       = (const float*)d_in[3];
    const float* W_in       = (const float*)d_in[4];
    const float* conv_w     = (const float*)d_in[5];
    const float* conv_b     = (const float*)d_in[6];
    const float* W_x        = (const float*)d_in[7];
    const float* log_A      = (const float*)d_in[8];
    const float* D_param    = (const float*)d_in[9];
    const float* W_out      = (const float*)d_in[10];
    float* out = (float*)d_out;

    void *p_xn, *p_Win, *p_Wout, *p_Wx, *p_xz, *p_xcb, *p_xpraw, *p_g;
    cudaGetSymbolAddress(&p_xn,    g_xn);
    cudaGetSymbolAddress(&p_Win,   g_Win);
    cudaGetSymbolAddress(&p_Wout,  g_Wout);
    cudaGetSymbolAddress(&p_Wx,    g_Wx);
    cudaGetSymbolAddress(&p_xz,    g_xz);
    cudaGetSymbolAddress(&p_xcb,   g_xcb);
    cudaGetSymbolAddress(&p_xpraw, g_xpraw);
    cudaGetSymbolAddress(&p_g,     g_g);

    static int smem_set = 0;
    if (!smem_set) {
        cudaFuncSetAttribute(gemm_k, cudaFuncAttributeMaxDynamicSharedMemorySize, GSMEM);
        smem_set = 1;
    }

    cvt_all_k<<<(T1+T2+T3+255)/256, 256>>>(W_in, W_out, W_x);

    ln_k<<<NROW, 256>>>(x, ln_w, ln_b);

    // GEMM1: xz[2048,4096] = xn[2048,1024] @ W_in[1024,4096]
    gemm_k<<<dim3(2*DI/BN, NROW/BM, 1), 128, GSMEM>>>((const __nv_bfloat16*)p_xn,
                                                      (const __nv_bfloat16*)p_Win,
                                                      (float*)p_xz, nullptr, 2*DI, DM, DM, 0);

    conv_k<<<dim3(DI/256, NROW/CL), 256>>>(conv_w, conv_b);

    // xp GEMM (split-K=8)
    gemm_k<<<dim3(WXN/BN, NROW/BM, KSPL), 128, GSMEM>>>((const __nv_bfloat16*)p_xcb,
                                                        (const __nv_bfloat16*)p_Wx,
                                                        (float*)p_xpraw, nullptr, WXN, DI, DI/KSPL,
                                                        (size_t)NROW*WXN);

    xpost_k<<<NROW, 64>>>();
    sums_k<<<BQ*NC, TCH>>>();

    scanA_k<<<dim3(DI/256, BQ, NC), 256>>>(log_A, D_param);
    scanB_k<<<(BQ*DI*DS)/256, 256>>>(log_A, init_state);
    scanC_k<<<dim3(DI/256, BQ, NC), 256>>>(log_A);

    // GEMM2 (+fused residual): out = x + g[2048,2048] @ W_out[2048,1024]
    gemm_k<<<dim3(DM/BN, NROW/BM, 1), 128, GSMEM>>>((const __nv_bfloat16*)p_g,
                                                    (const __nv_bfloat16*)p_Wout,
                                                    out, x, DM, DI, DI, 0);
}